// round 6
// baseline (speedup 1.0000x reference)
#include <cuda_runtime.h>
#include <cuda_fp16.h>
#include <cstdint>

// ============================================================================
// RBF: out[i][j] = exp(-0.5 * ||x_i - y_j||^2 / sigma^2), N=M=8192, D=64.
// sqd = xn_i + yn_j - 2*(x_i . y_j). Cross term via mma.sync fp16 HMMA.
// Exact fp16 hi/lo split, 3-term product hi*hi + hi*lo + lo*hi (lo*lo ~2^-22
// dropped). R5: operands stored as K=128 [hi|lo]; the three terms reuse
// loaded fragments (LDSM -33%). Epilogue stages through smem for fully
// coalesced STG.128 (store wavefronts -75%).
// ============================================================================

#define NROWS 8192
#define DDIM 64
#define KHALF 64
#define KSTORE 128          // [hi(64) | lo(64)]
#define LDA2 136            // smem stride in halves (272 B; conflict-free ldmatrix)
#define TILE 128
#define OSTRIDE 132         // staging stride in floats (528 B)

// -------- device scratch (static; allocation-guard safe) --------
__device__ __align__(16) __half g_A[(size_t)NROWS * KSTORE];   // 2 MB
__device__ __align__(16) __half g_B[(size_t)NROWS * KSTORE];   // 2 MB
__device__ float g_xn[NROWS];
__device__ float g_yn[NROWS];

__device__ __forceinline__ uint32_t smem_u32(const void* p) {
    uint32_t a;
    asm("{ .reg .u64 t; cvta.to.shared.u64 t, %1; cvt.u32.u64 %0, t; }" : "=r"(a) : "l"(p));
    return a;
}

__device__ __forceinline__ void mma16816(float* d, const uint32_t* a, const uint32_t* b) {
    asm volatile(
        "mma.sync.aligned.m16n8k16.row.col.f32.f16.f16.f32 "
        "{%0,%1,%2,%3}, {%4,%5,%6,%7}, {%8,%9}, {%0,%1,%2,%3};"
        : "+f"(d[0]), "+f"(d[1]), "+f"(d[2]), "+f"(d[3])
        : "r"(a[0]), "r"(a[1]), "r"(a[2]), "r"(a[3]), "r"(b[0]), "r"(b[1]));
}
__device__ __forceinline__ void ldsm4(uint32_t* r, uint32_t addr) {
    asm volatile("ldmatrix.sync.aligned.m8n8.x4.shared.b16 {%0,%1,%2,%3}, [%4];"
        : "=r"(r[0]), "=r"(r[1]), "=r"(r[2]), "=r"(r[3]) : "r"(addr));
}

// ============================================================================
// prep: fp32 -> (hi, lo) fp16 split, K=128 [hi|lo] operands + fp32 norms
// ============================================================================
__global__ void prep_kernel(const float* __restrict__ x, const float* __restrict__ y) {
    int wid = threadIdx.x >> 5, lane = threadIdx.x & 31;
    int rg = blockIdx.x * 8 + wid;
    bool isx = rg < NROWS;
    int row = isx ? rg : rg - NROWS;
    const float* src = isx ? x : y;

    float v0 = src[(size_t)row * DDIM + lane];
    float v1 = src[(size_t)row * DDIM + lane + 32];
    __half h0 = __float2half_rn(v0);
    __half h1 = __float2half_rn(v1);
    __half l0 = __float2half_rn(v0 - __half2float(h0));
    __half l1 = __float2half_rn(v1 - __half2float(h1));

    __half* dst = (isx ? g_A : g_B) + (size_t)row * KSTORE;
    dst[lane]      = h0; dst[lane + 32] = h1;   // hi
    dst[64 + lane] = l0; dst[96 + lane] = l1;   // lo

    float s = v0 * v0 + v1 * v1;
    #pragma unroll
    for (int o = 16; o; o >>= 1) s += __shfl_xor_sync(0xffffffffu, s, o);
    if (lane == 0) (isx ? g_xn : g_yn)[row] = s;
}

// ============================================================================
// main: 128x128 tile per CTA, 8 warps (2x4), warp tile 64x32.
// smem: operands (2 x 128 x 136 halves = 69632 B) reused as fp32 staging
// (128 x 132 floats = 67584 B) for the coalesced-store epilogue.
// ============================================================================
#define SMEM_OPS   (2 * TILE * LDA2 * 2)        // 69632 B
#define SMEM_TOTAL (SMEM_OPS + 2 * TILE * 4)    // + norms = 70656 B

__global__ __launch_bounds__(256, 2)
void rbf_kernel(const float* __restrict__ sigma, float* __restrict__ out) {
    extern __shared__ char smem[];
    __half* sA = (__half*)smem;
    __half* sB = sA + TILE * LDA2;
    float*  sO = (float*)smem;                  // staging (reuses operand smem)
    float*  s_xn = (float*)(smem + SMEM_OPS);
    float*  s_yn = s_xn + TILE;

    int tid = threadIdx.x;
    int tile_n = blockIdx.x, tile_m = blockIdx.y;

    // stage norms
    if (tid < TILE)       s_xn[tid]        = g_xn[tile_m * TILE + tid];
    else                  s_yn[tid - TILE] = g_yn[tile_n * TILE + tid - TILE];

    // stage operand tiles (row-major, 128 halves/row, stride LDA2)
    const uint4* gA = (const uint4*)(g_A + (size_t)tile_m * TILE * KSTORE);
    const uint4* gB = (const uint4*)(g_B + (size_t)tile_n * TILE * KSTORE);
    #pragma unroll
    for (int i = tid; i < TILE * (KSTORE / 8); i += 256) {
        int r = i >> 4, c = i & 15;
        *(uint4*)(sA + r * LDA2 + c * 8) = gA[i];
    }
    #pragma unroll
    for (int i = tid; i < TILE * (KSTORE / 8); i += 256) {
        int r = i >> 4, c = i & 15;
        *(uint4*)(sB + r * LDA2 + c * 8) = gB[i];
    }
    __syncthreads();

    int w = tid >> 5, lane = tid & 31;
    int warp_m = w >> 2, warp_n = w & 3;
    int m_base = warp_m * 64, n_base = warp_n * 32;
    int g = lane >> 3, tr = lane & 7;

    // ldmatrix bases (bytes). A .x4: g -> (rows m+{0,8}, k+{0,8});
    // B .x4 non-trans: g -> (rows n+{0,8} via g>>1, k+{0,8} via g&1).
    uint32_t a_sm = smem_u32(sA), b_sm = smem_u32(sB);
    uint32_t aBase = a_sm + (uint32_t)(((m_base + (g & 1) * 8 + tr) * LDA2 + (g >> 1) * 8) * 2);
    uint32_t bBase = b_sm + (uint32_t)(((n_base + (g >> 1) * 8 + tr) * LDA2 + (g & 1) * 8) * 2);

    float acc[4][4][4];
    #pragma unroll
    for (int mf = 0; mf < 4; ++mf)
        #pragma unroll
        for (int nf = 0; nf < 4; ++nf)
            #pragma unroll
            for (int r = 0; r < 4; ++r) acc[mf][nf][r] = 0.f;

    // 4 k-chunks of 16 over the hi segment; lo at byte offset +128.
    #pragma unroll 1
    for (int ks = 0; ks < KHALF / 16; ++ks) {
        uint32_t kb = (uint32_t)(ks * 32);          // 16 halves = 32 B

        uint32_t a_hi[4][4], a_lo[4][4];
        #pragma unroll
        for (int mf = 0; mf < 4; ++mf) {
            uint32_t ad = aBase + (uint32_t)(mf * 16 * LDA2 * 2) + kb;
            ldsm4(a_hi[mf], ad);
            ldsm4(a_lo[mf], ad + KHALF * 2);
        }
        uint32_t b_hi[4][2], b_lo[4][2];
        #pragma unroll
        for (int p = 0; p < 2; ++p) {
            uint32_t bd = bBase + (uint32_t)(p * 16 * LDA2 * 2) + kb;
            uint32_t rh[4], rl[4];
            ldsm4(rh, bd);
            ldsm4(rl, bd + KHALF * 2);
            b_hi[2 * p][0] = rh[0]; b_hi[2 * p][1] = rh[1];
            b_hi[2 * p + 1][0] = rh[2]; b_hi[2 * p + 1][1] = rh[3];
            b_lo[2 * p][0] = rl[0]; b_lo[2 * p][1] = rl[1];
            b_lo[2 * p + 1][0] = rl[2]; b_lo[2 * p + 1][1] = rl[3];
        }

        // 3-term accumulation reusing fragments: hi*hi + hi*lo + lo*hi
        #pragma unroll
        for (int mf = 0; mf < 4; ++mf)
            #pragma unroll
            for (int nf = 0; nf < 4; ++nf) {
                mma16816(acc[mf][nf], a_hi[mf], b_hi[nf]);
                mma16816(acc[mf][nf], a_hi[mf], b_lo[nf]);
                mma16816(acc[mf][nf], a_lo[mf], b_hi[nf]);
            }
    }

    // gather norms BEFORE staging overwrites nothing (norms live past SMEM_OPS)
    float sg = *sigma;
    float k2 = -0.7213475204444817f / (sg * sg);
    int r0 = lane >> 2;           // 0..7
    int c0 = (lane & 3) * 2;      // 0,2,4,6

    __syncthreads();              // all LDSM done -> safe to overwrite operands

    // epilogue phase 1: exp into fp32 staging buffer
    #pragma unroll
    for (int mf = 0; mf < 4; ++mf) {
        float xnA = s_xn[m_base + mf * 16 + r0];
        float xnB = s_xn[m_base + mf * 16 + r0 + 8];
        #pragma unroll
        for (int nf = 0; nf < 4; ++nf) {
            int col = n_base + nf * 8 + c0;
            float yn0 = s_yn[col], yn1 = s_yn[col + 1];
            float* d = acc[mf][nf];
            float q0 = fmaxf(fmaf(-2.f, d[0], xnA + yn0), 0.f);
            float q1 = fmaxf(fmaf(-2.f, d[1], xnA + yn1), 0.f);
            float q2 = fmaxf(fmaf(-2.f, d[2], xnB + yn0), 0.f);
            float q3 = fmaxf(fmaf(-2.f, d[3], xnB + yn1), 0.f);
            float2 o01, o23;
            o01.x = exp2f(q0 * k2); o01.y = exp2f(q1 * k2);
            o23.x = exp2f(q2 * k2); o23.y = exp2f(q3 * k2);
            int rowA = m_base + mf * 16 + r0;
            *reinterpret_cast<float2*>(sO + rowA * OSTRIDE + col)       = o01;
            *reinterpret_cast<float2*>(sO + (rowA + 8) * OSTRIDE + col) = o23;
        }
    }
    __syncthreads();

    // epilogue phase 2: one row per warp-iter, LDS.128 -> STG.128 (coalesced)
    size_t orow0 = (size_t)(tile_m * TILE) * 8192u + (size_t)(tile_n * TILE);
    #pragma unroll
    for (int i = 0; i < 16; ++i) {
        int row = w * 16 + i;
        float4 v = *reinterpret_cast<const float4*>(sO + row * OSTRIDE + lane * 4);
        *reinterpret_cast<float4*>(out + orow0 + (size_t)row * 8192u + lane * 4) = v;
    }
}

// ============================================================================
extern "C" void kernel_launch(void* const* d_in, const int* in_sizes, int n_in,
                              void* d_out, int out_size) {
    (void)in_sizes; (void)n_in; (void)out_size;
    const float* x     = (const float*)d_in[0];
    const float* y     = (const float*)d_in[1];
    const float* sigma = (const float*)d_in[2];
    float* out = (float*)d_out;

    cudaFuncSetAttribute(rbf_kernel, cudaFuncAttributeMaxDynamicSharedMemorySize, SMEM_TOTAL);

    prep_kernel<<<(2 * NROWS) / 8, 256>>>(x, y);
    rbf_kernel<<<dim3(NROWS / TILE, NROWS / TILE), 256, SMEM_TOTAL>>>(sigma, out);
}

// round 9
// speedup vs baseline: 1.8150x; 1.8150x over previous
#include <cuda_runtime.h>
#include <cuda_fp16.h>
#include <cstdint>

// ============================================================================
// RBF: out[i][j] = exp(-0.5 * ||x_i - y_j||^2 / sigma^2), N=M=8192, D=64.
// sqd = xn_i + yn_j - 2*(x_i . y_j). Cross term via mma.sync fp16 HMMA.
// Exact fp16 hi/lo split, 3-term product hi*hi + hi*lo + lo*hi (lo*lo ~2^-22
// dropped). R7/R8: operands stored K=128 [hi|lo]; three fragment-reuse MMA
// passes (LDSM -33% vs R5). Epilogue = R5's direct STG.64 (staging epilogue
// of R6 regressed and is reverted). Resubmitted verbatim after R8 infra fail.
// ============================================================================

#define NROWS 8192
#define DDIM 64
#define KHALF 64
#define KSTORE 128          // [hi(64) | lo(64)]
#define LDA2 136            // smem stride in halves (272 B; 272%128=16 -> conflict-free)
#define TILE 128

// -------- device scratch (static; allocation-guard safe) --------
__device__ __align__(16) __half g_A[(size_t)NROWS * KSTORE];   // 2 MB
__device__ __align__(16) __half g_B[(size_t)NROWS * KSTORE];   // 2 MB
__device__ float g_xn[NROWS];
__device__ float g_yn[NROWS];

__device__ __forceinline__ uint32_t smem_u32(const void* p) {
    uint32_t a;
    asm("{ .reg .u64 t; cvta.to.shared.u64 t, %1; cvt.u32.u64 %0, t; }" : "=r"(a) : "l"(p));
    return a;
}

__device__ __forceinline__ void mma16816(float* d, const uint32_t* a, const uint32_t* b) {
    asm volatile(
        "mma.sync.aligned.m16n8k16.row.col.f32.f16.f16.f32 "
        "{%0,%1,%2,%3}, {%4,%5,%6,%7}, {%8,%9}, {%0,%1,%2,%3};"
        : "+f"(d[0]), "+f"(d[1]), "+f"(d[2]), "+f"(d[3])
        : "r"(a[0]), "r"(a[1]), "r"(a[2]), "r"(a[3]), "r"(b[0]), "r"(b[1]));
}
__device__ __forceinline__ void ldsm4(uint32_t* r, uint32_t addr) {
    asm volatile("ldmatrix.sync.aligned.m8n8.x4.shared.b16 {%0,%1,%2,%3}, [%4];"
        : "=r"(r[0]), "=r"(r[1]), "=r"(r[2]), "=r"(r[3]) : "r"(addr));
}

// ============================================================================
// prep: fp32 -> (hi, lo) fp16 split, K=128 [hi|lo] operands + fp32 norms
// ============================================================================
__global__ void prep_kernel(const float* __restrict__ x, const float* __restrict__ y) {
    int wid = threadIdx.x >> 5, lane = threadIdx.x & 31;
    int rg = blockIdx.x * 8 + wid;
    bool isx = rg < NROWS;
    int row = isx ? rg : rg - NROWS;
    const float* src = isx ? x : y;

    float v0 = src[(size_t)row * DDIM + lane];
    float v1 = src[(size_t)row * DDIM + lane + 32];
    __half h0 = __float2half_rn(v0);
    __half h1 = __float2half_rn(v1);
    __half l0 = __float2half_rn(v0 - __half2float(h0));
    __half l1 = __float2half_rn(v1 - __half2float(h1));

    __half* dst = (isx ? g_A : g_B) + (size_t)row * KSTORE;
    dst[lane]      = h0; dst[lane + 32] = h1;   // hi
    dst[64 + lane] = l0; dst[96 + lane] = l1;   // lo

    float s = v0 * v0 + v1 * v1;
    #pragma unroll
    for (int o = 16; o; o >>= 1) s += __shfl_xor_sync(0xffffffffu, s, o);
    if (lane == 0) (isx ? g_xn : g_yn)[row] = s;
}

// ============================================================================
// main: 128x128 tile per CTA, 8 warps (2x4), warp tile 64x32,
// K=128 [hi|lo] in smem, 3-pass fragment-reuse MMA, direct-store epilogue.
// ============================================================================
#define SMEM_OPS   (2 * TILE * LDA2 * 2)        // 69632 B
#define SMEM_TOTAL (SMEM_OPS + 2 * TILE * 4)    // + norms = 70656 B

__global__ __launch_bounds__(256, 2)
void rbf_kernel(const float* __restrict__ sigma, float* __restrict__ out) {
    extern __shared__ char smem[];
    __half* sA = (__half*)smem;
    __half* sB = sA + TILE * LDA2;
    float*  s_xn = (float*)(smem + SMEM_OPS);
    float*  s_yn = s_xn + TILE;

    int tid = threadIdx.x;
    int tile_n = blockIdx.x, tile_m = blockIdx.y;

    // stage norms
    if (tid < TILE)       s_xn[tid]        = g_xn[tile_m * TILE + tid];
    else                  s_yn[tid - TILE] = g_yn[tile_n * TILE + tid - TILE];

    // stage operand tiles (row-major, 128 halves/row, stride LDA2)
    const uint4* gA = (const uint4*)(g_A + (size_t)tile_m * TILE * KSTORE);
    const uint4* gB = (const uint4*)(g_B + (size_t)tile_n * TILE * KSTORE);
    #pragma unroll
    for (int i = tid; i < TILE * (KSTORE / 8); i += 256) {
        int r = i >> 4, c = i & 15;
        *(uint4*)(sA + r * LDA2 + c * 8) = gA[i];
    }
    #pragma unroll
    for (int i = tid; i < TILE * (KSTORE / 8); i += 256) {
        int r = i >> 4, c = i & 15;
        *(uint4*)(sB + r * LDA2 + c * 8) = gB[i];
    }
    __syncthreads();

    int w = tid >> 5, lane = tid & 31;
    int warp_m = w >> 2, warp_n = w & 3;
    int m_base = warp_m * 64, n_base = warp_n * 32;
    int g = lane >> 3, tr = lane & 7;

    // ldmatrix bases (bytes). A .x4: g -> (rows m+{0,8}, k+{0,8});
    // B .x4 non-trans: g -> (rows n+{0,8} via g>>1, k+{0,8} via g&1).
    uint32_t a_sm = smem_u32(sA), b_sm = smem_u32(sB);
    uint32_t aBase = a_sm + (uint32_t)(((m_base + (g & 1) * 8 + tr) * LDA2 + (g >> 1) * 8) * 2);
    uint32_t bBase = b_sm + (uint32_t)(((n_base + (g >> 1) * 8 + tr) * LDA2 + (g & 1) * 8) * 2);

    float acc[4][4][4];
    #pragma unroll
    for (int mf = 0; mf < 4; ++mf)
        #pragma unroll
        for (int nf = 0; nf < 4; ++nf)
            #pragma unroll
            for (int r = 0; r < 4; ++r) acc[mf][nf][r] = 0.f;

    // 4 k-chunks of 16 over the hi segment; lo at byte offset +128.
    #pragma unroll 1
    for (int ks = 0; ks < KHALF / 16; ++ks) {
        uint32_t kb = (uint32_t)(ks * 32);          // 16 halves = 32 B

        uint32_t a_hi[4][4], a_lo[4][4];
        #pragma unroll
        for (int mf = 0; mf < 4; ++mf) {
            uint32_t ad = aBase + (uint32_t)(mf * 16 * LDA2 * 2) + kb;
            ldsm4(a_hi[mf], ad);
            ldsm4(a_lo[mf], ad + KHALF * 2);
        }
        uint32_t b_hi[4][2], b_lo[4][2];
        #pragma unroll
        for (int p = 0; p < 2; ++p) {
            uint32_t bd = bBase + (uint32_t)(p * 16 * LDA2 * 2) + kb;
            uint32_t rh[4], rl[4];
            ldsm4(rh, bd);
            ldsm4(rl, bd + KHALF * 2);
            b_hi[2 * p][0] = rh[0]; b_hi[2 * p][1] = rh[1];
            b_hi[2 * p + 1][0] = rh[2]; b_hi[2 * p + 1][1] = rh[3];
            b_lo[2 * p][0] = rl[0]; b_lo[2 * p][1] = rl[1];
            b_lo[2 * p + 1][0] = rl[2]; b_lo[2 * p + 1][1] = rl[3];
        }

        // three 16-MMA sweeps: each acc touched once per sweep -> 15
        // independent MMAs between dependent touches (no RAW bubbles).
        #pragma unroll
        for (int mf = 0; mf < 4; ++mf)
            #pragma unroll
            for (int nf = 0; nf < 4; ++nf)
                mma16816(acc[mf][nf], a_hi[mf], b_hi[nf]);
        #pragma unroll
        for (int mf = 0; mf < 4; ++mf)
            #pragma unroll
            for (int nf = 0; nf < 4; ++nf)
                mma16816(acc[mf][nf], a_hi[mf], b_lo[nf]);
        #pragma unroll
        for (int mf = 0; mf < 4; ++mf)
            #pragma unroll
            for (int nf = 0; nf < 4; ++nf)
                mma16816(acc[mf][nf], a_lo[mf], b_hi[nf]);
    }

    // fused epilogue (R5 direct-store): q = max(xn+yn-2c, 0); out = exp2(q*k2)
    float sg = *sigma;
    float k2 = -0.7213475204444817f / (sg * sg);
    int r0 = lane >> 2;           // 0..7
    int c0 = (lane & 3) * 2;      // 0,2,4,6

    size_t out_row0 = (size_t)(tile_m * TILE + m_base + r0) * 8192u
                    + (size_t)(tile_n * TILE + n_base + c0);
    #pragma unroll
    for (int mf = 0; mf < 4; ++mf) {
        float xnA = s_xn[m_base + mf * 16 + r0];
        float xnB = s_xn[m_base + mf * 16 + r0 + 8];
        #pragma unroll
        for (int nf = 0; nf < 4; ++nf) {
            int col = n_base + nf * 8 + c0;
            float yn0 = s_yn[col], yn1 = s_yn[col + 1];
            float* d = acc[mf][nf];
            float q0 = fmaxf(fmaf(-2.f, d[0], xnA + yn0), 0.f);
            float q1 = fmaxf(fmaf(-2.f, d[1], xnA + yn1), 0.f);
            float q2 = fmaxf(fmaf(-2.f, d[2], xnB + yn0), 0.f);
            float q3 = fmaxf(fmaf(-2.f, d[3], xnB + yn1), 0.f);
            float2 o01, o23;
            o01.x = exp2f(q0 * k2); o01.y = exp2f(q1 * k2);
            o23.x = exp2f(q2 * k2); o23.y = exp2f(q3 * k2);
            size_t base = out_row0 + (size_t)(mf * 16) * 8192u + (size_t)(nf * 8);
            *reinterpret_cast<float2*>(out + base)               = o01;
            *reinterpret_cast<float2*>(out + base + 8u * 8192u)  = o23;
        }
    }
}

// ============================================================================
extern "C" void kernel_launch(void* const* d_in, const int* in_sizes, int n_in,
                              void* d_out, int out_size) {
    (void)in_sizes; (void)n_in; (void)out_size;
    const float* x     = (const float*)d_in[0];
    const float* y     = (const float*)d_in[1];
    const float* sigma = (const float*)d_in[2];
    float* out = (float*)d_out;

    cudaFuncSetAttribute(rbf_kernel, cudaFuncAttributeMaxDynamicSharedMemorySize, SMEM_TOTAL);

    prep_kernel<<<(2 * NROWS) / 8, 256>>>(x, y);
    rbf_kernel<<<dim3(NROWS / TILE, NROWS / TILE), 256, SMEM_TOTAL>>>(sigma, out);
}